// round 4
// baseline (speedup 1.0000x reference)
#include <cuda_runtime.h>
#include <cuda_bf16.h>

#define THREADS 256
#define NWARP   8
#define NBA     1024     // 10-bit level-A histogram
#define CAP     2048     // rank-path candidate cap

// Scratch: boost factors (n <= 16384 supported; actual n = 4096)
__device__ float g_bf[16384];

__global__ void boost_kernel(const float* __restrict__ duty,
                             const int* __restrict__ kp, int n) {
    int i = blockIdx.x * blockDim.x + threadIdx.x;
    if (i < n) {
        float td = (float)(*kp) / (float)n;
        g_bf[i] = expf(td - duty[i]);   // boostStrength = 1.0
    }
}

// Monotone float -> uint key: key(a) >= key(b)  <=>  a >= b  (for non-NaN)
__device__ __forceinline__ unsigned f2key(float f) {
    unsigned u = __float_as_uint(f);
    return u ^ (unsigned)(((int)u >> 31) | 0x80000000);
}
// Inverse transform
__device__ __forceinline__ float key2f(unsigned k) {
    unsigned m = ((int)k < 0) ? 0x80000000u : 0xFFFFFFFFu;
    return __uint_as_float(k ^ m);
}

struct Sm {
    union {
        unsigned hist[NBA];   // 4KB, dead after scan
        unsigned list[CAP];   // 8KB candidate list (overlay)
    } u;
    unsigned wtot[NWARP];
    unsigned sPrefix, sKr, sCnt, sNum, sThr;
};

template <int EPV>  // float4 elements per thread per row
__global__ __launch_bounds__(THREADS, 6)
void kwinner_kernel(const float* __restrict__ x,
                    const int* __restrict__ kp,
                    float* __restrict__ out, int n) {
    const int row  = blockIdx.x;
    const int t    = threadIdx.x;
    const int lane = t & 31;
    const int wid  = t >> 5;
    constexpr int NK = EPV * 4;

    __shared__ Sm s;

    // Zero 1024-bin histogram: one uint4 store per thread
    ((uint4*)s.u.hist)[t] = make_uint4(0, 0, 0, 0);

    const float4* xrow = (const float4*)(x + (size_t)row * n);
    const float4* bfv  = (const float4*)g_bf;

    unsigned key[NK];
    #pragma unroll
    for (int j = 0; j < EPV; j++) {
        int f = t + j * THREADS;
        float4 xv = xrow[f];
        float4 bf = bfv[f];
        key[j*4+0] = f2key(xv.x * bf.x);
        key[j*4+1] = f2key(xv.y * bf.y);
        key[j*4+2] = f2key(xv.z * bf.z);
        key[j*4+3] = f2key(xv.w * bf.w);
    }
    __syncthreads();   // hist zeroed

    // 10-bit histogram, warp-aggregated atomics (data clusters in few bins)
    #pragma unroll
    for (int e = 0; e < NK; e++) {
        unsigned d = key[e] >> 22;
        unsigned m = __match_any_sync(0xFFFFFFFFu, d);
        if ((unsigned)lane == __ffs(m) - 1u)
            atomicAdd(&s.u.hist[d], (unsigned)__popc(m));
    }
    if (t == 0) s.sNum = 0;
    __syncthreads();

    const unsigned k0 = (unsigned)__ldg(kp);

    // Suffix-count scan: thread t owns bins [4t, 4t+3]
    uint4 h4 = ((const uint4*)s.u.hist)[t];
    unsigned hh[4] = {h4.x, h4.y, h4.z, h4.w};
    unsigned tot = hh[0] + hh[1] + hh[2] + hh[3];
    unsigned v = tot;   // becomes sum over lanes [lane..31]
    #pragma unroll
    for (int off = 1; off < 32; off <<= 1) {
        unsigned u = __shfl_down_sync(0xFFFFFFFFu, v, off);
        if (lane + off < 32) v += u;
    }
    if (lane == 0) s.wtot[wid] = v;
    __syncthreads();

    unsigned run = v - tot;                 // suffix above own 4-bin chunk (in-warp)
    for (int j = wid + 1; j < NWARP; j++)   // higher warps (broadcast reads)
        run += s.wtot[j];
    #pragma unroll
    for (int i = 3; i >= 0; i--) {
        unsigned nxt = run;      // suffix(bin+1)
        run += hh[i];            // suffix(bin)
        if (run >= k0 && nxt < k0) {   // unique crossing bin
            s.sPrefix = (unsigned)(t * 4 + i) << 22;
            s.sKr     = k0 - nxt;
            s.sCnt    = hh[i];
        }
    }
    __syncthreads();
    const unsigned prefix = s.sPrefix;
    const unsigned kr     = s.sKr;
    const unsigned C1     = s.sCnt;

    unsigned thresh;
    if (C1 <= CAP) {
        // Compact crossing-bin candidates (overlays hist; hist reads are done)
        #pragma unroll
        for (int e = 0; e < NK; e++) {
            unsigned kk = key[e];
            if ((kk >> 22) == (prefix >> 22))
                s.u.list[atomicAdd(&s.sNum, 1u)] = kk;
        }
        __syncthreads();
        const unsigned C = s.sNum;   // == C1 <= CAP

        // Parallel rank: candidate with (gt < kr <= ge) is the kr-th largest
        // in the bin == overall k-th largest. Inner loop is smem-broadcast.
        for (unsigned i = t; i < C; i += THREADS) {
            unsigned ki = s.u.list[i];
            unsigned gt = 0, ge = 0;
            #pragma unroll 8
            for (unsigned j = 0; j < C; j++) {
                unsigned lj = s.u.list[j];
                gt += (lj > ki)  ? 1u : 0u;
                ge += (lj >= ki) ? 1u : 0u;
            }
            if (gt < kr && ge >= kr) s.sThr = ki;   // ties write same value
        }
        __syncthreads();
        thresh = s.sThr;
    } else {
        // Degenerate-row fallback (exactness guarantee): block-wide greedy
        // bit-descent on the remaining 22 bits, counting over ALL keys vs k0.
        unsigned thr = prefix;
        for (int b = 21; b >= 0; b--) {
            unsigned test = thr | (1u << b);
            unsigned c = 0;
            #pragma unroll
            for (int e = 0; e < NK; e++) c += (key[e] >= test) ? 1u : 0u;
            c = __reduce_add_sync(0xFFFFFFFFu, c);
            if (lane == 0) s.wtot[wid] = c;
            __syncthreads();
            unsigned cb = 0;
            #pragma unroll
            for (int j = 0; j < NWARP; j++) cb += s.wtot[j];
            if (cb >= k0) thr = test;
            __syncthreads();   // wtot reusable next iteration
        }
        thresh = thr;   // identical in all threads
    }

    // Output: x = boosted / bf (fast division, ~2ulp; tolerance is 1e-3)
    float4* orow = (float4*)(out + (size_t)row * n);
    #pragma unroll
    for (int j = 0; j < EPV; j++) {
        int f = t + j * THREADS;
        float4 bf = bfv[f];   // L1-hot: same table for every CTA on the SM
        float4 o;
        o.x = (key[j*4+0] >= thresh) ? __fdividef(key2f(key[j*4+0]), bf.x) : 0.0f;
        o.y = (key[j*4+1] >= thresh) ? __fdividef(key2f(key[j*4+1]), bf.y) : 0.0f;
        o.z = (key[j*4+2] >= thresh) ? __fdividef(key2f(key[j*4+2]), bf.z) : 0.0f;
        o.w = (key[j*4+3] >= thresh) ? __fdividef(key2f(key[j*4+3]), bf.w) : 0.0f;
        orow[f] = o;
    }
}

extern "C" void kernel_launch(void* const* d_in, const int* in_sizes, int n_in,
                              void* d_out, int out_size) {
    const float* x    = (const float*)d_in[0];
    const float* duty = (const float*)d_in[1];
    const int*   kp   = (const int*)d_in[2];
    float*       out  = (float*)d_out;

    int n    = in_sizes[1];          // 4096
    int rows = in_sizes[0] / n;      // 8192

    boost_kernel<<<(n + 255) / 256, 256>>>(duty, kp, n);

    int epv = n / (THREADS * 4);
    switch (epv) {
        case 1:  kwinner_kernel<1><<<rows, THREADS>>>(x, kp, out, n);  break;
        case 2:  kwinner_kernel<2><<<rows, THREADS>>>(x, kp, out, n);  break;
        case 4:  kwinner_kernel<4><<<rows, THREADS>>>(x, kp, out, n);  break;
        case 8:  kwinner_kernel<8><<<rows, THREADS>>>(x, kp, out, n);  break;
        case 16: kwinner_kernel<16><<<rows, THREADS>>>(x, kp, out, n); break;
        default: break; // unsupported shape (not expected for this problem)
    }
}

// round 5
// speedup vs baseline: 4.0631x; 4.0631x over previous
#include <cuda_runtime.h>
#include <cuda_bf16.h>

#define THREADS 256
#define NWARP   8
#define NBINS   2048     // positive-key histogram, key bits [30:20]
#define BPT     8        // bins per thread
#define CAP     2048     // rank-path candidate cap (overlays hist)

// Scratch: boost factors (n <= 16384 supported; actual n = 4096)
__device__ float g_bf[16384];

__global__ void boost_kernel(const float* __restrict__ duty,
                             const int* __restrict__ kp, int n) {
    int i = blockIdx.x * blockDim.x + threadIdx.x;
    if (i < n) {
        float td = (float)(*kp) / (float)n;
        g_bf[i] = expf(td - duty[i]);   // boostStrength = 1.0
    }
}

// Monotone float -> uint key: key(a) >= key(b)  <=>  a >= b  (for non-NaN)
__device__ __forceinline__ unsigned f2key(float f) {
    unsigned u = __float_as_uint(f);
    return u ^ (unsigned)(((int)u >> 31) | 0x80000000);
}

struct Sm {
    union {
        unsigned hist[NBINS];   // 8KB, dead after the in-register scan
        unsigned list[CAP];     // candidate overlay
    } u;
    unsigned wtot[NWARP];
    unsigned sPrefix, sKr, sCnt, sNum, sThr;
};

template <int EPV>  // float4 elements per thread per row
__global__ __launch_bounds__(THREADS, 6)
void kwinner_kernel(const float* __restrict__ x,
                    const int* __restrict__ kp,
                    float* __restrict__ out, int n) {
    const int row  = blockIdx.x;
    const int t    = threadIdx.x;
    const int lane = t & 31;
    const int wid  = t >> 5;
    constexpr int NK = EPV * 4;

    __shared__ Sm s;

    // Zero histogram: two uint4 stores per thread
    ((uint4*)s.u.hist)[t]           = make_uint4(0, 0, 0, 0);
    ((uint4*)s.u.hist)[t + THREADS] = make_uint4(0, 0, 0, 0);

    const float4* xrow = (const float4*)(x + (size_t)row * n);
    const float4* bfv  = (const float4*)g_bf;

    unsigned key[NK];
    #pragma unroll
    for (int j = 0; j < EPV; j++) {
        int f = t + j * THREADS;
        float4 xv = xrow[f];
        float4 bf = bfv[f];
        key[j*4+0] = f2key(xv.x * bf.x);
        key[j*4+1] = f2key(xv.y * bf.y);
        key[j*4+2] = f2key(xv.z * bf.z);
        key[j*4+3] = f2key(xv.w * bf.w);
    }
    if (t == 0) { s.sNum = 0; s.sCnt = 0xFFFFFFFFu; }
    __syncthreads();   // hist zeroed

    // Histogram POSITIVE keys only (MSB set): bin = key bits [30:20]
    #pragma unroll
    for (int e = 0; e < NK; e++) {
        unsigned kk = key[e];
        if ((int)kk < 0)   // MSB set => boosted value >= +0.0
            atomicAdd(&s.u.hist[(kk >> 20) & (NBINS - 1)], 1u);
    }
    __syncthreads();

    const unsigned k0 = (unsigned)__ldg(kp);

    // Suffix-count scan; thread t owns bins [8t, 8t+8), kept in registers
    uint4 a = ((const uint4*)s.u.hist)[t * 2];
    uint4 b = ((const uint4*)s.u.hist)[t * 2 + 1];
    unsigned hh[BPT] = {a.x, a.y, a.z, a.w, b.x, b.y, b.z, b.w};
    unsigned tot = 0;
    #pragma unroll
    for (int i = 0; i < BPT; i++) tot += hh[i];

    unsigned v = tot;   // becomes sum over lanes [lane..31]
    #pragma unroll
    for (int off = 1; off < 32; off <<= 1) {
        unsigned u = __shfl_down_sync(0xFFFFFFFFu, v, off);
        if (lane + off < 32) v += u;
    }
    if (lane == 0) s.wtot[wid] = v;
    __syncthreads();

    unsigned run = v - tot;                 // in-warp suffix above own chunk
    for (int j = wid + 1; j < NWARP; j++)   // higher warps (broadcast reads)
        run += s.wtot[j];
    #pragma unroll
    for (int i = BPT - 1; i >= 0; i--) {
        unsigned nxt = run;      // suffix(bin+1)
        run += hh[i];            // suffix(bin)
        if (run >= k0 && nxt < k0) {   // unique crossing bin
            s.sPrefix = (0x800u + (unsigned)(t * BPT + i)) << 20;
            s.sKr     = k0 - nxt;
            s.sCnt    = hh[i];
        }
    }
    __syncthreads();
    const unsigned prefix = s.sPrefix;
    const unsigned kr     = s.sKr;
    const unsigned C1     = s.sCnt;   // 0xFFFFFFFF if positives < k0

    unsigned thresh;
    if (C1 <= CAP) {
        // Compact crossing-bin candidates (overlays hist; reads are done)
        #pragma unroll
        for (int e = 0; e < NK; e++) {
            unsigned kk = key[e];
            if ((kk >> 20) == (prefix >> 20))
                s.u.list[atomicAdd(&s.sNum, 1u)] = kk;
        }
        __syncthreads();
        const unsigned C = s.sNum;   // == C1

        // Parallel rank: candidate with (gt < kr <= ge) is the kr-th largest
        // in the bin == overall k-th largest. Inner loop is smem-broadcast.
        for (unsigned i = t; i < C; i += THREADS) {
            unsigned ki = s.u.list[i];
            unsigned gt = 0, ge = 0;
            #pragma unroll 4
            for (unsigned j = 0; j < C; j++) {
                unsigned lj = s.u.list[j];
                gt += (lj > ki)  ? 1u : 0u;
                ge += (lj >= ki) ? 1u : 0u;
            }
            if (gt < kr && ge >= kr) s.sThr = ki;   // ties write same value
        }
        __syncthreads();
        thresh = s.sThr;
    } else {
        // Exactness fallback (positives < k0 or giant bin): block-wide greedy
        // bit-descent over all 32 key bits. Never taken on benchmark data.
        unsigned thr = 0;
        for (int b = 31; b >= 0; b--) {
            unsigned test = thr | (1u << b);
            unsigned c = 0;
            #pragma unroll
            for (int e = 0; e < NK; e++) c += (key[e] >= test) ? 1u : 0u;
            c = __reduce_add_sync(0xFFFFFFFFu, c);
            if (lane == 0) s.wtot[wid] = c;
            __syncthreads();
            unsigned cb = 0;
            #pragma unroll
            for (int j = 0; j < NWARP; j++) cb += s.wtot[j];
            if (cb >= k0) thr = test;
            __syncthreads();
        }
        thresh = thr;   // identical in all threads
    }

    // Output: EXACT passthrough of original x (re-read; row is L1/L2-hot),
    // masked by the register-resident keys. No division, no MUFU.
    float4* orow = (float4*)(out + (size_t)row * n);
    #pragma unroll
    for (int j = 0; j < EPV; j++) {
        int f = t + j * THREADS;
        float4 xv = xrow[f];
        float4 o;
        o.x = (key[j*4+0] >= thresh) ? xv.x : 0.0f;
        o.y = (key[j*4+1] >= thresh) ? xv.y : 0.0f;
        o.z = (key[j*4+2] >= thresh) ? xv.z : 0.0f;
        o.w = (key[j*4+3] >= thresh) ? xv.w : 0.0f;
        orow[f] = o;
    }
}

extern "C" void kernel_launch(void* const* d_in, const int* in_sizes, int n_in,
                              void* d_out, int out_size) {
    const float* x    = (const float*)d_in[0];
    const float* duty = (const float*)d_in[1];
    const int*   kp   = (const int*)d_in[2];
    float*       out  = (float*)d_out;

    int n    = in_sizes[1];          // 4096
    int rows = in_sizes[0] / n;      // 8192

    boost_kernel<<<(n + 255) / 256, 256>>>(duty, kp, n);

    int epv = n / (THREADS * 4);
    switch (epv) {
        case 1:  kwinner_kernel<1><<<rows, THREADS>>>(x, kp, out, n);  break;
        case 2:  kwinner_kernel<2><<<rows, THREADS>>>(x, kp, out, n);  break;
        case 4:  kwinner_kernel<4><<<rows, THREADS>>>(x, kp, out, n);  break;
        case 8:  kwinner_kernel<8><<<rows, THREADS>>>(x, kp, out, n);  break;
        case 16: kwinner_kernel<16><<<rows, THREADS>>>(x, kp, out, n); break;
        default: break; // unsupported shape (not expected for this problem)
    }
}